// round 4
// baseline (speedup 1.0000x reference)
#include <cuda_runtime.h>
#include <cuda_bf16.h>
#include <math.h>

#define N_NODES 50000
#define N_EDGES 600000
#define N_GRAPHS 64

// ------------------- scratch (no allocation allowed) -------------------
__device__ float g_T[N_NODES * 128];     // GEMM output (transformed features)
__device__ float g_H[N_NODES * 128];     // aggregated layer output / next input
__device__ float g_dinv[N_NODES];
__device__ int   g_deg[N_NODES];
__device__ int   g_off[N_NODES + 1];
__device__ int   g_cur[N_NODES];
__device__ int   g_ebuf[N_EDGES];        // CSR: source row per slot (by destination)
__device__ float g_pool[N_GRAPHS * 64];
__device__ int   g_cnt[N_GRAPHS];
__device__ float g_fc1[N_GRAPHS * 32];

// ------------------- zero init -------------------
__global__ void zero_kernel() {
    int i = blockIdx.x * blockDim.x + threadIdx.x;
    if (i < N_NODES) { g_deg[i] = 0; g_cur[i] = 0; }
    if (i < N_GRAPHS * 64) g_pool[i] = 0.f;
    if (i < N_GRAPHS) g_cnt[i] = 0;
}

// ------------------- CSR build (edge_index is int32: JAX default x64-disabled
// downcasts the requested int64) -------------------
__global__ void count_kernel(const int* __restrict__ ei) {
    int e = blockIdx.x * blockDim.x + threadIdx.x;
    if (e < N_EDGES) {
        int c = ei[N_EDGES + e];
        if (c >= 0 && c < N_NODES) atomicAdd(&g_deg[c], 1);
    }
}

__global__ void dinv_kernel() {
    int i = blockIdx.x * blockDim.x + threadIdx.x;
    if (i < N_NODES) g_dinv[i] = rsqrtf((float)(g_deg[i] + 1));  // +1 self loop
}

// single-block exclusive scan of g_deg -> g_off
__global__ void scan_kernel() {
    __shared__ int warp_sums[32];
    __shared__ int s_carry;
    int tid = threadIdx.x;  // 1024 threads
    if (tid == 0) s_carry = 0;
    __syncthreads();
    for (int base = 0; base < N_NODES; base += 1024) {
        int i = base + tid;
        int v = (i < N_NODES) ? g_deg[i] : 0;
        int x = v;
        #pragma unroll
        for (int d = 1; d < 32; d <<= 1) {
            int t = __shfl_up_sync(0xFFFFFFFFu, x, d);
            if ((tid & 31) >= d) x += t;
        }
        if ((tid & 31) == 31) warp_sums[tid >> 5] = x;
        __syncthreads();
        if (tid < 32) {
            int w = warp_sums[tid];
            #pragma unroll
            for (int d = 1; d < 32; d <<= 1) {
                int t = __shfl_up_sync(0xFFFFFFFFu, w, d);
                if (tid >= d) w += t;
            }
            warp_sums[tid] = w;  // inclusive scan of warp totals
        }
        __syncthreads();
        int warp_off = (tid >= 32) ? warp_sums[(tid >> 5) - 1] : 0;
        int incl = x + warp_off;
        int carry_local = s_carry;
        if (i < N_NODES) g_off[i] = carry_local + (incl - v);
        __syncthreads();
        if (tid == 0) s_carry += warp_sums[31];
        __syncthreads();
    }
    if (tid == 0) g_off[N_NODES] = s_carry;  // == N_EDGES
}

__global__ void fill_kernel(const int* __restrict__ ei) {
    int e = blockIdx.x * blockDim.x + threadIdx.x;
    if (e < N_EDGES) {
        int c = ei[N_EDGES + e];
        int r = ei[e];
        if (c >= 0 && c < N_NODES && r >= 0 && r < N_NODES) {
            int p = atomicAdd(&g_cur[c], 1);
            g_ebuf[g_off[c] + p] = r;
        }
    }
}

// ------------------- GEMM: g_T = act(src) @ W  (src:[n,FIN], W:[FIN,FOUT])
// SRC_EXT=true reads from the X argument; else reads g_H directly.
template <int FIN, int FOUT, bool RELU_IN, bool SRC_EXT>
__global__ __launch_bounds__(256) void gemm_kernel(
    const float* __restrict__ X, const float* __restrict__ W, int n)
{
    constexpr int TN = FOUT / 32;  // cols per thread (4 or 2)
    __shared__ float Xs[64][33];
    __shared__ float Ws[32][FOUT];
    const float* __restrict__ src = SRC_EXT ? X : (const float*)g_H;
    int m0 = blockIdx.x * 64;
    int tx = threadIdx.x & 31, ty = threadIdx.x >> 5;  // ty: 0..7
    float acc[8][TN];
    #pragma unroll
    for (int r = 0; r < 8; r++)
        #pragma unroll
        for (int c = 0; c < TN; c++) acc[r][c] = 0.f;

    for (int k0 = 0; k0 < FIN; k0 += 32) {
        #pragma unroll
        for (int j = 0; j < 8; j++) {
            int r = ty * 8 + j;
            int gr = m0 + r;
            float v = (gr < n) ? src[(size_t)gr * FIN + k0 + tx] : 0.f;
            if (RELU_IN) v = fmaxf(v, 0.f);
            Xs[r][tx] = v;
        }
        #pragma unroll
        for (int j = 0; j < (32 * FOUT) / (256 * 4); j++) {
            int idx = (threadIdx.x + j * 256) * 4;
            int kk = idx / FOUT, cc = idx % FOUT;
            *(float4*)&Ws[kk][cc] = *(const float4*)&W[(size_t)(k0 + kk) * FOUT + cc];
        }
        __syncthreads();
        #pragma unroll
        for (int kk = 0; kk < 32; kk++) {
            float wv[TN];
            #pragma unroll
            for (int c = 0; c < TN; c++) wv[c] = Ws[kk][tx * TN + c];
            #pragma unroll
            for (int r = 0; r < 8; r++) {
                float xv = Xs[ty * 8 + r][kk];
                #pragma unroll
                for (int c = 0; c < TN; c++) acc[r][c] += xv * wv[c];
            }
        }
        __syncthreads();
    }
    #pragma unroll
    for (int r = 0; r < 8; r++) {
        int gr = m0 + ty * 8 + r;
        if (gr < n) {
            #pragma unroll
            for (int c = 0; c < TN; c++)
                g_T[(size_t)gr * FOUT + tx * TN + c] = acc[r][c];
        }
    }
}

// ------------------- Aggregation: g_H[i] = b + dinv_i^2*T[i] + sum_e dinv_r*dinv_i*T[r]
template <int F>
__global__ __launch_bounds__(256) void agg_kernel(const float* __restrict__ bias)
{
    int warp = (blockIdx.x * blockDim.x + threadIdx.x) >> 5;
    if (warp >= N_NODES) return;
    int lane = threadIdx.x & 31;
    constexpr int V = F / 32;  // 4 or 2
    int i = warp;
    float dii = g_dinv[i];
    float acc[V];
    {
        const float* Ti = g_T + (size_t)i * F + lane * V;
        float dii2 = dii * dii;
        #pragma unroll
        for (int c = 0; c < V; c++) acc[c] = bias[lane * V + c] + dii2 * Ti[c];
    }
    int s = g_off[i], e = g_off[i + 1];
    for (int p = s; p < e; p++) {
        int r = g_ebuf[p];
        float w = dii * g_dinv[r];
        const float* Tr = g_T + (size_t)r * F + lane * V;
        if (V == 4) {
            float4 t = *(const float4*)Tr;
            acc[0] += w * t.x; acc[1] += w * t.y;
            acc[2 % V] += w * t.z; acc[3 % V] += w * t.w;
        } else {
            float2 t = *(const float2*)Tr;
            acc[0] += w * t.x; acc[1] += w * t.y;
        }
    }
    float* Hi = g_H + (size_t)i * F + lane * V;
    #pragma unroll
    for (int c = 0; c < V; c++) Hi[c] = acc[c];
}

// ------------------- mean pool over sorted batch ids (input relu'd here) -----
__global__ void pool_kernel(const int* __restrict__ batch)
{
    int c = threadIdx.x & 63;   // channel
    int sub = threadIdx.x >> 6; // 0..3
    int n0 = blockIdx.x * 512;
    float acc = 0.f; int cur = -1; int cnt = 0;
    for (int j = sub; j < 512; j += 4) {
        int node = n0 + j;
        if (node >= N_NODES) break;
        int b = batch[node];
        if (b < 0 || b >= N_GRAPHS) continue;
        if (b != cur) {
            if (cur >= 0) {
                atomicAdd(&g_pool[cur * 64 + c], acc);
                if (c == 0) atomicAdd(&g_cnt[cur], cnt);
            }
            cur = b; acc = 0.f; cnt = 0;
        }
        acc += fmaxf(g_H[(size_t)node * 64 + c], 0.f);
        cnt++;
    }
    if (cur >= 0) {
        atomicAdd(&g_pool[cur * 64 + c], acc);
        if (c == 0) atomicAdd(&g_cnt[cur], cnt);
    }
}

// ------------------- tiny MLP head -------------------
__global__ void fc1_kernel(const float* __restrict__ Wf1, const float* __restrict__ bf1) {
    int g = blockIdx.x; int j = threadIdx.x;  // grid 64, block 32
    float inv = 1.f / fmaxf((float)g_cnt[g], 1.f);
    float s = bf1[j];
    for (int k = 0; k < 64; k++) s += g_pool[g * 64 + k] * inv * Wf1[k * 32 + j];
    g_fc1[g * 32 + j] = fmaxf(s, 0.f);
}

__global__ void fc2_kernel(const float* __restrict__ Wf2, const float* __restrict__ bf2,
                           float* __restrict__ out) {
    int g = blockIdx.x; int o = threadIdx.x;  // grid 64, block 10
    float s = bf2[o];
    for (int j = 0; j < 32; j++) s += g_fc1[g * 32 + j] * Wf2[j * 10 + o];
    out[g * 10 + o] = s;
}

// ------------------- launch: kernel launches ONLY, no other CUDA API --------
extern "C" void kernel_launch(void* const* d_in, const int* in_sizes, int n_in,
                              void* d_out, int out_size)
{
    const float* x     = (const float*)d_in[0];
    const int*   ei    = (const int*)d_in[1];
    const int*   batch = (const int*)d_in[2];
    const float* W1  = (const float*)d_in[3];
    const float* b1  = (const float*)d_in[4];
    const float* W2  = (const float*)d_in[5];
    const float* b2  = (const float*)d_in[6];
    const float* W3  = (const float*)d_in[7];
    const float* b3  = (const float*)d_in[8];
    const float* Wf1 = (const float*)d_in[9];
    const float* bf1 = (const float*)d_in[10];
    const float* Wf2 = (const float*)d_in[11];
    const float* bf2 = (const float*)d_in[12];
    float* out = (float*)d_out;

    zero_kernel<<<(N_NODES + 255) / 256, 256>>>();

    // CSR build
    count_kernel<<<(N_EDGES + 255) / 256, 256>>>(ei);
    dinv_kernel<<<(N_NODES + 255) / 256, 256>>>();
    scan_kernel<<<1, 1024>>>();
    fill_kernel<<<(N_EDGES + 255) / 256, 256>>>(ei);

    int gemm_blocks = (N_NODES + 63) / 64;
    int agg_blocks  = (N_NODES * 32 + 255) / 256;

    // layer 1: 128 -> 128 (external input)
    gemm_kernel<128, 128, false, true><<<gemm_blocks, 256>>>(x, W1, N_NODES);
    agg_kernel<128><<<agg_blocks, 256>>>(b1);
    // layer 2: 128 -> 128 (g_H input, relu)
    gemm_kernel<128, 128, true, false><<<gemm_blocks, 256>>>(nullptr, W2, N_NODES);
    agg_kernel<128><<<agg_blocks, 256>>>(b2);
    // layer 3: 128 -> 64 (g_H input, relu)
    gemm_kernel<128, 64, true, false><<<gemm_blocks, 256>>>(nullptr, W3, N_NODES);
    agg_kernel<64><<<agg_blocks, 256>>>(b3);

    // mean pool (relu fused) + MLP head
    pool_kernel<<<(N_NODES + 511) / 512, 256>>>(batch);
    fc1_kernel<<<N_GRAPHS, 32>>>(Wf1, bf1);
    fc2_kernel<<<N_GRAPHS, 10>>>(Wf2, bf2, out);
}